// round 1
// baseline (speedup 1.0000x reference)
#include <cuda_runtime.h>
#include <cuda_fp16.h>
#include <math.h>
#include <stdint.h>

// ============================================================================
// Decoder_33208687133135 on GB300 (sm_103a)
//
// z = koopman^T per batch -> rows Z (131072 x 64)
// H1 = tanh(Z@W1+b1); H2 = tanh(H1@W2+b2); H3 = tanh(H2@W3+b3)
// ds[r] = H3[r,:] @ W4[:, r%64] + b4[r%64]   (diagonal only!)
// out = (x - dt) * exp(-ds)
//
// Precision scheme: every fp32 operand a is split a = hi + lo (fp16 each);
// GEMMs accumulate Ah*Bh + Ah*Bl + Al*Bh in fp32 -> ~22-bit effective
// mantissa, rel_err ~1e-6 (safe vs 1e-3 threshold).
// ============================================================================

#define NDIM      512
#define CHUNK     16384          // rows per chunk (multiple of 64)
#define NCHUNK    8              // 8 * 16384 = 131072 = B*D
#define R_TOTAL   131072

// -------- static device scratch (allocation-free rule) ----------------------
__device__ __half g_b0h[CHUNK * NDIM];   // ping buffer hi  (16 MB)
__device__ __half g_b0l[CHUNK * NDIM];   // ping buffer lo
__device__ __half g_b1h[CHUNK * NDIM];   // pong buffer hi
__device__ __half g_b1l[CHUNK * NDIM];   // pong buffer lo
__device__ __half g_zh[R_TOTAL * 64];    // Z hi (full M)   (16 MB)
__device__ __half g_zl[R_TOTAL * 64];    // Z lo
// split weights: per MLP W1(64x512)=32768, W2=262144, W3=262144 -> 557056
#define OFF_W1 0
#define OFF_W2 32768
#define OFF_W3 294912
#define MLP_STRIDE 557056
__device__ __half g_wh[2 * MLP_STRIDE];
__device__ __half g_wl[2 * MLP_STRIDE];
__device__ float  g_ds[CHUNK];           // per-chunk s-diagonal

// ---------------------------------------------------------------------------
// fp32 -> (hi, lo) fp16 split of a flat array
__global__ __launch_bounds__(256) void split_kernel(
    const float* __restrict__ src, __half* __restrict__ dh,
    __half* __restrict__ dl, int n)
{
    int i = blockIdx.x * 256 + threadIdx.x;
    if (i < n) {
        float v = src[i];
        __half h = __float2half_rn(v);
        dh[i] = h;
        dl[i] = __float2half_rn(v - __half2float(h));
    }
}

// koopman (B, 64, 64) -> Z rows: Z[(b*64+i)*64 + l] = koopman[b][l][i], split
__global__ __launch_bounds__(256) void transpose_split_kernel(
    const float* __restrict__ koop, __half* __restrict__ zh,
    __half* __restrict__ zl)
{
    __shared__ float s[64][65];
    int b = blockIdx.x;
    const float* src = koop + (size_t)b * 4096;
    for (int idx = threadIdx.x; idx < 4096; idx += 256)
        s[idx >> 6][idx & 63] = src[idx];           // s[l][i]
    __syncthreads();
    for (int idx = threadIdx.x; idx < 4096; idx += 256) {
        int i = idx >> 6, l = idx & 63;
        float v = s[l][i];
        __half h = __float2half_rn(v);
        size_t o = ((size_t)b * 64 + i) * 64 + l;
        zh[o] = h;
        zl[o] = __float2half_rn(v - __half2float(h));
    }
}

// ---------------------------------------------------------------------------
#define MMA16816(d, a0, a1, a2, a3, b0, b1)                                   \
    asm volatile(                                                             \
        "mma.sync.aligned.m16n8k16.row.col.f32.f16.f16.f32 "                  \
        "{%0,%1,%2,%3}, {%4,%5,%6,%7}, {%8,%9}, {%0,%1,%2,%3};\n"             \
        : "+f"(d[0]), "+f"(d[1]), "+f"(d[2]), "+f"(d[3])                      \
        : "r"(a0), "r"(a1), "r"(a2), "r"(a3), "r"(b0), "r"(b1))

// Fused GEMM + bias + tanh + re-split.
//   A (CHUNK x K) as hi/lo fp16, W (K x 512) as hi/lo fp16, bias fp32.
//   O = split(tanh(A@W + bias)), (CHUNK x 512).
// CTA tile 64x64, BK=64, 256 threads = 8 warps (4 along M x 2 along N),
// warp tile 16x32, mma.sync m16n8k16, 3 split products per fragment pair.
__global__ __launch_bounds__(256) void gemm_split_kernel(
    const __half* __restrict__ Ah, const __half* __restrict__ Al, int K,
    const __half* __restrict__ Wh, const __half* __restrict__ Wl,
    const float* __restrict__ bias,
    __half* __restrict__ Oh, __half* __restrict__ Ol)
{
    __shared__ __align__(16) __half As_h[64][72];
    __shared__ __align__(16) __half As_l[64][72];
    __shared__ __align__(16) __half Bs_h[64][72];   // W transposed: [n][k]
    __shared__ __align__(16) __half Bs_l[64][72];

    const int tid  = threadIdx.x;
    const int m0   = blockIdx.y * 64;
    const int n0   = blockIdx.x * 64;
    const int lane = tid & 31, wid = tid >> 5;
    const int wm = wid & 3, wn = wid >> 2;
    const int grp = lane >> 2, q = lane & 3;

    float acc[4][4];
#pragma unroll
    for (int j = 0; j < 4; j++)
#pragma unroll
        for (int i = 0; i < 4; i++) acc[j][i] = 0.0f;

    for (int k0 = 0; k0 < K; k0 += 64) {
        // ---- stage A tile (64x64) hi/lo, 8B vector loads -------------------
        for (int c = tid; c < 1024; c += 256) {
            int r = c >> 4, kc = (c & 15) << 2;
            size_t src = (size_t)(m0 + r) * K + k0 + kc;
            *reinterpret_cast<uint2*>(&As_h[r][kc]) =
                *reinterpret_cast<const uint2*>(Ah + src);
            *reinterpret_cast<uint2*>(&As_l[r][kc]) =
                *reinterpret_cast<const uint2*>(Al + src);
        }
        // ---- stage W tile transposed: Bs[n][k] = W[k0+k][n0+n] -------------
        for (int c = tid; c < 4096; c += 256) {
            int kr = c >> 6, nc = c & 63;
            size_t src = (size_t)(k0 + kr) * NDIM + n0 + nc;
            Bs_h[nc][kr] = Wh[src];
            Bs_l[nc][kr] = Wl[src];
        }
        __syncthreads();

#pragma unroll
        for (int ks = 0; ks < 64; ks += 16) {
            uint32_t ah[4], al[4];
            const int ar0 = wm * 16 + grp;
            ah[0] = *reinterpret_cast<const uint32_t*>(&As_h[ar0    ][ks + q * 2    ]);
            ah[1] = *reinterpret_cast<const uint32_t*>(&As_h[ar0 + 8][ks + q * 2    ]);
            ah[2] = *reinterpret_cast<const uint32_t*>(&As_h[ar0    ][ks + q * 2 + 8]);
            ah[3] = *reinterpret_cast<const uint32_t*>(&As_h[ar0 + 8][ks + q * 2 + 8]);
            al[0] = *reinterpret_cast<const uint32_t*>(&As_l[ar0    ][ks + q * 2    ]);
            al[1] = *reinterpret_cast<const uint32_t*>(&As_l[ar0 + 8][ks + q * 2    ]);
            al[2] = *reinterpret_cast<const uint32_t*>(&As_l[ar0    ][ks + q * 2 + 8]);
            al[3] = *reinterpret_cast<const uint32_t*>(&As_l[ar0 + 8][ks + q * 2 + 8]);
#pragma unroll
            for (int j = 0; j < 4; j++) {
                const int ncol = wn * 32 + j * 8 + grp;
                uint32_t bh0 = *reinterpret_cast<const uint32_t*>(&Bs_h[ncol][ks + q * 2    ]);
                uint32_t bh1 = *reinterpret_cast<const uint32_t*>(&Bs_h[ncol][ks + q * 2 + 8]);
                uint32_t bl0 = *reinterpret_cast<const uint32_t*>(&Bs_l[ncol][ks + q * 2    ]);
                uint32_t bl1 = *reinterpret_cast<const uint32_t*>(&Bs_l[ncol][ks + q * 2 + 8]);
                MMA16816(acc[j], ah[0], ah[1], ah[2], ah[3], bh0, bh1);
                MMA16816(acc[j], ah[0], ah[1], ah[2], ah[3], bl0, bl1);
                MMA16816(acc[j], al[0], al[1], al[2], al[3], bh0, bh1);
            }
        }
        __syncthreads();
    }

    // ---- epilogue: + bias, tanh, re-split, store hi/lo ---------------------
#pragma unroll
    for (int j = 0; j < 4; j++) {
        const int col = n0 + wn * 32 + j * 8 + q * 2;
        const int row = m0 + wm * 16 + grp;
        const float bb0 = bias[col], bb1 = bias[col + 1];
        float v00 = tanhf(acc[j][0] + bb0);
        float v01 = tanhf(acc[j][1] + bb1);
        float v10 = tanhf(acc[j][2] + bb0);
        float v11 = tanhf(acc[j][3] + bb1);
        __half h00 = __float2half_rn(v00), h01 = __float2half_rn(v01);
        __half h10 = __float2half_rn(v10), h11 = __float2half_rn(v11);
        __half l00 = __float2half_rn(v00 - __half2float(h00));
        __half l01 = __float2half_rn(v01 - __half2float(h01));
        __half l10 = __float2half_rn(v10 - __half2float(h10));
        __half l11 = __float2half_rn(v11 - __half2float(h11));
        size_t o0 = (size_t)row * NDIM + col;
        size_t o1 = o0 + (size_t)8 * NDIM;
        *reinterpret_cast<__half2*>(Oh + o0) = __halves2half2(h00, h01);
        *reinterpret_cast<__half2*>(Oh + o1) = __halves2half2(h10, h11);
        *reinterpret_cast<__half2*>(Ol + o0) = __halves2half2(l00, l01);
        *reinterpret_cast<__half2*>(Ol + o1) = __halves2half2(l10, l11);
    }
}

// ---------------------------------------------------------------------------
// diag: ds[r] = H3[r,:] @ W4[:, r%64] + b4[r%64]   (one warp per row)
__global__ __launch_bounds__(256) void diag_kernel(
    const __half* __restrict__ Hh, const __half* __restrict__ Hl,
    const float* __restrict__ W4, const float* __restrict__ b4,
    float* __restrict__ ds)
{
    const int wid = threadIdx.x >> 5, lane = threadIdx.x & 31;
    const int r = blockIdx.x * 8 + wid;
    const int i = r & 63;
    const __half* ph = Hh + (size_t)r * NDIM;
    const __half* pl = Hl + (size_t)r * NDIM;
    float sum = 0.0f;
#pragma unroll
    for (int k = lane; k < NDIM; k += 32) {
        float a = __half2float(ph[k]) + __half2float(pl[k]);
        sum += a * W4[(size_t)k * 64 + i];
    }
#pragma unroll
    for (int off = 16; off; off >>= 1)
        sum += __shfl_xor_sync(0xffffffffu, sum, off);
    if (lane == 0) ds[r] = sum + b4[i];
}

// final: out[r] = (x[r] - dt[r]) * exp(-ds[r]), dt computed like diag
__global__ __launch_bounds__(256) void final_kernel(
    const __half* __restrict__ Hh, const __half* __restrict__ Hl,
    const float* __restrict__ W4, const float* __restrict__ b4,
    const float* __restrict__ x, const float* __restrict__ ds,
    float* __restrict__ out)
{
    const int wid = threadIdx.x >> 5, lane = threadIdx.x & 31;
    const int r = blockIdx.x * 8 + wid;
    const int i = r & 63;
    const __half* ph = Hh + (size_t)r * NDIM;
    const __half* pl = Hl + (size_t)r * NDIM;
    float sum = 0.0f;
#pragma unroll
    for (int k = lane; k < NDIM; k += 32) {
        float a = __half2float(ph[k]) + __half2float(pl[k]);
        sum += a * W4[(size_t)k * 64 + i];
    }
#pragma unroll
    for (int off = 16; off; off >>= 1)
        sum += __shfl_xor_sync(0xffffffffu, sum, off);
    if (lane == 0) {
        float dt = sum + b4[i];
        out[r] = (x[r] - dt) * expf(-ds[r]);
    }
}

// ---------------------------------------------------------------------------
extern "C" void kernel_launch(void* const* d_in, const int* in_sizes, int n_in,
                              void* d_out, int out_size)
{
    (void)in_sizes; (void)n_in; (void)out_size;

    const float* x    = (const float*)d_in[0];
    const float* koop = (const float*)d_in[1];
    const float* sW1 = (const float*)d_in[2];  const float* sb1 = (const float*)d_in[3];
    const float* sW2 = (const float*)d_in[4];  const float* sb2 = (const float*)d_in[5];
    const float* sW3 = (const float*)d_in[6];  const float* sb3 = (const float*)d_in[7];
    const float* sW4 = (const float*)d_in[8];  const float* sb4 = (const float*)d_in[9];
    const float* tW1 = (const float*)d_in[10]; const float* tb1 = (const float*)d_in[11];
    const float* tW2 = (const float*)d_in[12]; const float* tb2 = (const float*)d_in[13];
    const float* tW3 = (const float*)d_in[14]; const float* tb3 = (const float*)d_in[15];
    const float* tW4 = (const float*)d_in[16]; const float* tb4 = (const float*)d_in[17];
    float* out = (float*)d_out;

    __half *b0h, *b0l, *b1h, *b1l, *zh, *zl, *wh, *wl;
    float* ds;
    cudaGetSymbolAddress((void**)&b0h, g_b0h);
    cudaGetSymbolAddress((void**)&b0l, g_b0l);
    cudaGetSymbolAddress((void**)&b1h, g_b1h);
    cudaGetSymbolAddress((void**)&b1l, g_b1l);
    cudaGetSymbolAddress((void**)&zh,  g_zh);
    cudaGetSymbolAddress((void**)&zl,  g_zl);
    cudaGetSymbolAddress((void**)&wh,  g_wh);
    cudaGetSymbolAddress((void**)&wl,  g_wl);
    cudaGetSymbolAddress((void**)&ds,  g_ds);

    // split weights (W4 stays fp32 for the diag kernels)
    split_kernel<<<(32768 + 255) / 256, 256>>>(sW1, wh + OFF_W1, wl + OFF_W1, 32768);
    split_kernel<<<(262144 + 255) / 256, 256>>>(sW2, wh + OFF_W2, wl + OFF_W2, 262144);
    split_kernel<<<(262144 + 255) / 256, 256>>>(sW3, wh + OFF_W3, wl + OFF_W3, 262144);
    split_kernel<<<(32768 + 255) / 256, 256>>>(tW1, wh + MLP_STRIDE + OFF_W1, wl + MLP_STRIDE + OFF_W1, 32768);
    split_kernel<<<(262144 + 255) / 256, 256>>>(tW2, wh + MLP_STRIDE + OFF_W2, wl + MLP_STRIDE + OFF_W2, 262144);
    split_kernel<<<(262144 + 255) / 256, 256>>>(tW3, wh + MLP_STRIDE + OFF_W3, wl + MLP_STRIDE + OFF_W3, 262144);

    // build Z = koopman^T rows (full M)
    transpose_split_kernel<<<2048, 256>>>(koop, zh, zl);

    dim3 ggrid(8, CHUNK / 64);   // (N tiles, M tiles)
    for (int c = 0; c < NCHUNK; c++) {
        size_t row0 = (size_t)c * CHUNK;
        // ---- s-MLP ----
        gemm_split_kernel<<<ggrid, 256>>>(zh + row0 * 64, zl + row0 * 64, 64,
                                          wh + OFF_W1, wl + OFF_W1, sb1, b0h, b0l);
        gemm_split_kernel<<<ggrid, 256>>>(b0h, b0l, 512,
                                          wh + OFF_W2, wl + OFF_W2, sb2, b1h, b1l);
        gemm_split_kernel<<<ggrid, 256>>>(b1h, b1l, 512,
                                          wh + OFF_W3, wl + OFF_W3, sb3, b0h, b0l);
        diag_kernel<<<CHUNK / 8, 256>>>(b0h, b0l, sW4, sb4, ds);
        // ---- t-MLP ----
        gemm_split_kernel<<<ggrid, 256>>>(zh + row0 * 64, zl + row0 * 64, 64,
                                          wh + MLP_STRIDE + OFF_W1, wl + MLP_STRIDE + OFF_W1,
                                          tb1, b0h, b0l);
        gemm_split_kernel<<<ggrid, 256>>>(b0h, b0l, 512,
                                          wh + MLP_STRIDE + OFF_W2, wl + MLP_STRIDE + OFF_W2,
                                          tb2, b1h, b1l);
        gemm_split_kernel<<<ggrid, 256>>>(b1h, b1l, 512,
                                          wh + MLP_STRIDE + OFF_W3, wl + MLP_STRIDE + OFF_W3,
                                          tb3, b0h, b0l);
        final_kernel<<<CHUNK / 8, 256>>>(b0h, b0l, tW4, tb4, x + row0, ds, out + row0);
    }
}

// round 2
// speedup vs baseline: 2.2441x; 2.2441x over previous
#include <cuda_runtime.h>
#include <cuda_fp16.h>
#include <math.h>
#include <stdint.h>

// ============================================================================
// Decoder_33208687133135 on GB300 (sm_103a) — Round 2
//
// Full-M formulation: M = 262144 rows = [s-MLP 131072 | t-MLP 131072].
// z row r (r<131072): Z[r][l] = koopman[r>>6][l][r&63]
// H1 = tanh(Z@W1+b1); H2 = tanh(H1@W2+b2); H3 = tanh(H2@W3+b3)
// ds[r] = H3_s[r] . sW4[:, r&63] + sb4 ; dt likewise from H3_t
// out = (x - dt) * exp(-ds)
//
// Precision: split-fp16 (hi+lo), 3 MMA products (AhBh + AhBl + AlBh), fp32 acc.
// GEMM: 128x64 CTA tile, BK=64, cp.async double buffer, ldmatrix.x4, mma.16816.
// ============================================================================

#define MTOT   262144            // 2 * 131072
#define HALF_M 131072
#define NDIM   512

// per-MLP transposed-weight layout (halves): W1t 512x64, W2t 512x512, W3t 512x512
#define OFF_W1 0
#define OFF_W2 32768
#define OFF_W3 294912
#define MLP_STRIDE 557056

// -------- static device scratch ---------------------------------------------
__device__ __half g_b0h[(size_t)MTOT * NDIM];
__device__ __half g_b0l[(size_t)MTOT * NDIM];
__device__ __half g_b1h[(size_t)MTOT * NDIM];
__device__ __half g_b1l[(size_t)MTOT * NDIM];
__device__ __half g_wh[2 * MLP_STRIDE];
__device__ __half g_wl[2 * MLP_STRIDE];
__device__ float  g_w4t[2 * 64 * 512];   // transposed W4: [i][k], s then t

// -------- PTX helpers --------------------------------------------------------
#define CP16(d, s) asm volatile("cp.async.cg.shared.global [%0], [%1], 16;" :: "r"(d), "l"(s))
#define CP_COMMIT  asm volatile("cp.async.commit_group;")
#define CP_WAIT(n) asm volatile("cp.async.wait_group %0;" :: "n"(n))

#define LDSM4(R, addr)                                                         \
    asm volatile("ldmatrix.sync.aligned.m8n8.x4.shared.b16 {%0,%1,%2,%3}, [%4];" \
        : "=r"(R[0]), "=r"(R[1]), "=r"(R[2]), "=r"(R[3]) : "r"(addr))

#define MMA(d, a, b0, b1)                                                      \
    asm volatile("mma.sync.aligned.m16n8k16.row.col.f32.f16.f16.f32 "          \
        "{%0,%1,%2,%3},{%4,%5,%6,%7},{%8,%9},{%0,%1,%2,%3};"                   \
        : "+f"(d[0]), "+f"(d[1]), "+f"(d[2]), "+f"(d[3])                       \
        : "r"(a[0]), "r"(a[1]), "r"(a[2]), "r"(a[3]), "r"(b0), "r"(b1))

// smem stage layout (bytes): Ah[128][72] @0, Al @18432, Bh[64][72] @36864, Bl @46080
#define STAGE_BYTES 55296
#define AL_OFF 18432
#define BH_OFF 36864
#define BL_REL 9216

// ---------------------------------------------------------------------------
// weight prep: transpose K x 512(or 64) fp32 -> [n][k] hi/lo fp16 (or fp32)
__device__ __forceinline__ void transpose_split_tile(
    const float* __restrict__ W, int K, int N,
    __half* __restrict__ Wth, __half* __restrict__ Wtl)
{
    __shared__ float t[32][33];
    int tx = threadIdx.x, ty = threadIdx.y;
    int k0 = blockIdx.x * 32, n0 = blockIdx.y * 32;
#pragma unroll
    for (int j = 0; j < 4; j++)
        t[ty + j * 8][tx] = W[(size_t)(k0 + ty + j * 8) * N + n0 + tx];
    __syncthreads();
#pragma unroll
    for (int j = 0; j < 4; j++) {
        int n = n0 + ty + j * 8;
        float v = t[tx][ty + j * 8];
        __half h = __float2half_rn(v);
        size_t o = (size_t)n * K + k0 + tx;
        Wth[o] = h;
        Wtl[o] = __float2half_rn(v - __half2float(h));
    }
}

__device__ __forceinline__ void transpose_f32_tile(
    const float* __restrict__ W, int K, int N, float* __restrict__ Wt)
{
    __shared__ float t2[32][33];
    int tx = threadIdx.x, ty = threadIdx.y;
    int k0 = blockIdx.x * 32, n0 = blockIdx.y * 32;
#pragma unroll
    for (int j = 0; j < 4; j++)
        t2[ty + j * 8][tx] = W[(size_t)(k0 + ty + j * 8) * N + n0 + tx];
    __syncthreads();
#pragma unroll
    for (int j = 0; j < 4; j++) {
        int n = n0 + ty + j * 8;
        Wt[(size_t)n * K + k0 + tx] = t2[tx][ty + j * 8];
    }
}

__global__ void prep_a(const float* sW1, const float* tW1,
                       const float* sW4, const float* tW4,
                       __half* wh, __half* wl, float* w4t)
{
    int z = blockIdx.z;
    if (z == 0)      { if (blockIdx.x < 2) transpose_split_tile(sW1, 64, 512, wh + OFF_W1, wl + OFF_W1); }
    else if (z == 1) { if (blockIdx.x < 2) transpose_split_tile(tW1, 64, 512, wh + MLP_STRIDE + OFF_W1, wl + MLP_STRIDE + OFF_W1); }
    else if (z == 2) { if (blockIdx.y < 2) transpose_f32_tile(sW4, 512, 64, w4t); }
    else             { if (blockIdx.y < 2) transpose_f32_tile(tW4, 512, 64, w4t + 32768); }
}

__global__ void prep_w23(const float* W2, const float* W3, __half* wh, __half* wl)
{
    if (blockIdx.z == 0) transpose_split_tile(W2, 512, 512, wh + OFF_W2, wl + OFF_W2);
    else                 transpose_split_tile(W3, 512, 512, wh + OFF_W3, wl + OFF_W3);
}

// ---------------------------------------------------------------------------
__device__ __forceinline__ void epilogue_store(
    float (&acc)[2][4][4], const float* __restrict__ bias,
    __half* __restrict__ Oh, __half* __restrict__ Ol,
    int m0, int n0, int wm, int wn, int grp, int q)
{
#pragma unroll
    for (int mi = 0; mi < 2; ++mi)
#pragma unroll
    for (int nj = 0; nj < 4; ++nj) {
        int row = m0 + wm * 32 + mi * 16 + grp;
        int col = n0 + wn * 32 + nj * 8 + q * 2;
        float bb0 = bias[col], bb1 = bias[col + 1];
        float v00 = tanhf(acc[mi][nj][0] + bb0);
        float v01 = tanhf(acc[mi][nj][1] + bb1);
        float v10 = tanhf(acc[mi][nj][2] + bb0);
        float v11 = tanhf(acc[mi][nj][3] + bb1);
        __half h00 = __float2half_rn(v00), h01 = __float2half_rn(v01);
        __half h10 = __float2half_rn(v10), h11 = __float2half_rn(v11);
        __half l00 = __float2half_rn(v00 - __half2float(h00));
        __half l01 = __float2half_rn(v01 - __half2float(h01));
        __half l10 = __float2half_rn(v10 - __half2float(h10));
        __half l11 = __float2half_rn(v11 - __half2float(h11));
        size_t o0 = (size_t)row * NDIM + col;
        size_t o1 = o0 + (size_t)8 * NDIM;
        *reinterpret_cast<__half2*>(Oh + o0) = __halves2half2(h00, h01);
        *reinterpret_cast<__half2*>(Oh + o1) = __halves2half2(h10, h11);
        *reinterpret_cast<__half2*>(Ol + o0) = __halves2half2(l00, l01);
        *reinterpret_cast<__half2*>(Ol + o1) = __halves2half2(l10, l11);
    }
}

// shared compute of one 64-deep k stage from smem buffer at byte base `cur`
__device__ __forceinline__ void compute_stage(
    uint32_t cur, const uint32_t offA[2], const uint32_t offB[2],
    float (&acc)[2][4][4])
{
#pragma unroll
    for (int ks = 0; ks < 64; ks += 16) {
        uint32_t ah[2][4], al_[2][4];
#pragma unroll
        for (int mi = 0; mi < 2; ++mi) {
            LDSM4(ah[mi],  cur + offA[mi] + ks * 2);
            LDSM4(al_[mi], cur + AL_OFF + offA[mi] + ks * 2);
        }
#pragma unroll
        for (int nj2 = 0; nj2 < 2; ++nj2) {
            uint32_t bh[4], bl[4];
            LDSM4(bh, cur + offB[nj2] + ks * 2);
            LDSM4(bl, cur + BL_REL + offB[nj2] + ks * 2);
#pragma unroll
            for (int mi = 0; mi < 2; ++mi) {
                MMA(acc[mi][nj2 * 2],     ah[mi],  bh[0], bh[1]);
                MMA(acc[mi][nj2 * 2],     ah[mi],  bl[0], bl[1]);
                MMA(acc[mi][nj2 * 2],     al_[mi], bh[0], bh[1]);
                MMA(acc[mi][nj2 * 2 + 1], ah[mi],  bh[2], bh[3]);
                MMA(acc[mi][nj2 * 2 + 1], ah[mi],  bl[2], bl[3]);
                MMA(acc[mi][nj2 * 2 + 1], al_[mi], bh[2], bh[3]);
            }
        }
    }
}

// ---------------------------------------------------------------------------
// K=512 GEMM with cp.async double buffering. O = split(tanh(A@Wt^T + b)).
__global__ __launch_bounds__(256) void gemm512_kernel(
    const __half* __restrict__ Ah, const __half* __restrict__ Al,
    const __half* __restrict__ WhS, const __half* __restrict__ WlS,
    const __half* __restrict__ WhT, const __half* __restrict__ WlT,
    const float* __restrict__ biasS, const float* __restrict__ biasT,
    __half* __restrict__ Oh, __half* __restrict__ Ol)
{
    extern __shared__ __half sm[];
    uint32_t sb = (uint32_t)__cvta_generic_to_shared(sm);
    const int tid = threadIdx.x, lane = tid & 31, wid = tid >> 5;
    const int wm = wid & 3, wn = wid >> 2, grp = lane >> 2, q = lane & 3;
    const int m0 = blockIdx.y * 128, n0 = blockIdx.x * 64;
    const bool isS = blockIdx.y < (gridDim.y >> 1);
    const __half* Wh = isS ? WhS : WhT;
    const __half* Wl = isS ? WlS : WlT;
    const float* bias = isS ? biasS : biasT;

    float acc[2][4][4];
#pragma unroll
    for (int a = 0; a < 2; a++)
#pragma unroll
        for (int b = 0; b < 4; b++)
#pragma unroll
            for (int c = 0; c < 4; c++) acc[a][b][c] = 0.0f;

    uint32_t offA[2], offB[2];
#pragma unroll
    for (int mi = 0; mi < 2; ++mi)
        offA[mi] = ((wm * 32 + mi * 16 + (lane & 15)) * 72 + (lane >> 4) * 8) * 2;
#pragma unroll
    for (int nj2 = 0; nj2 < 2; ++nj2)
        offB[nj2] = BH_OFF +
            ((wn * 32 + nj2 * 16 + (lane & 7) + ((lane >> 4) << 3)) * 72 +
             ((lane >> 3) & 1) * 8) * 2;

    // stage loader
    auto load_stage = [&](uint32_t base, int k0) {
#pragma unroll
        for (int i = 0; i < 4; i++) {
            int c = tid + i * 256;
            int r = c >> 3, kc = (c & 7) << 3;
            size_t g = (size_t)(m0 + r) * 512 + k0 + kc;
            uint32_t d = base + (r * 72 + kc) * 2;
            CP16(d, Ah + g);
            CP16(d + AL_OFF, Al + g);
        }
#pragma unroll
        for (int i = 0; i < 2; i++) {
            int c = tid + i * 256;
            int n = c >> 3, kc = (c & 7) << 3;
            size_t g = (size_t)(n0 + n) * 512 + k0 + kc;
            uint32_t d = base + BH_OFF + (n * 72 + kc) * 2;
            CP16(d, Wh + g);
            CP16(d + BL_REL, Wl + g);
        }
    };

    load_stage(sb, 0);
    CP_COMMIT;
    for (int it = 0; it < 8; ++it) {
        uint32_t cur = sb + (it & 1) * STAGE_BYTES;
        if (it < 7) {
            load_stage(sb + ((it + 1) & 1) * STAGE_BYTES, (it + 1) * 64);
            CP_COMMIT;
            CP_WAIT(1);
        } else {
            CP_WAIT(0);
        }
        __syncthreads();
        compute_stage(cur, offA, offB, acc);
        __syncthreads();
    }
    epilogue_store(acc, bias, Oh, Ol, m0, n0, wm, wn, grp, q);
}

// ---------------------------------------------------------------------------
// Layer-1 GEMM: A built on the fly from koopman (transpose + split), K=64.
__global__ __launch_bounds__(256) void gemm_l1_kernel(
    const float* __restrict__ koop,
    const __half* __restrict__ WhS, const __half* __restrict__ WlS,
    const __half* __restrict__ WhT, const __half* __restrict__ WlT,
    const float* __restrict__ biasS, const float* __restrict__ biasT,
    __half* __restrict__ Oh, __half* __restrict__ Ol)
{
    extern __shared__ __half sm[];
    uint32_t sb = (uint32_t)__cvta_generic_to_shared(sm);
    const int tid = threadIdx.x, lane = tid & 31, wid = tid >> 5;
    const int wm = wid & 3, wn = wid >> 2, grp = lane >> 2, q = lane & 3;
    const int m0 = blockIdx.y * 128, n0 = blockIdx.x * 64;
    const bool isS = blockIdx.y < (gridDim.y >> 1);
    const __half* Wh = isS ? WhS : WhT;
    const __half* Wl = isS ? WlS : WlT;
    const float* bias = isS ? biasS : biasT;

    // B tile (64 n x 64 k) via cp.async; W1t stride = 64
#pragma unroll
    for (int i = 0; i < 2; i++) {
        int c = tid + i * 256;
        int n = c >> 3, kc = (c & 7) << 3;
        size_t g = (size_t)(n0 + n) * 64 + kc;
        uint32_t d = sb + BH_OFF + (n * 72 + kc) * 2;
        CP16(d, Wh + g);
        CP16(d + BL_REL, Wl + g);
    }
    CP_COMMIT;

    // A tile (128 rows x 64 l) from koopman, transposed + split on the fly
#pragma unroll
    for (int i = 0; i < 32; i++) {
        int c = tid + i * 256;
        int rloc = c & 127, l = c >> 7;
        int zr = (m0 + rloc) & (HALF_M - 1);
        float v = koop[(size_t)(zr >> 6) * 4096 + l * 64 + (zr & 63)];
        __half h = __float2half_rn(v);
        sm[rloc * 72 + l] = h;
        sm[9216 + rloc * 72 + l] = __float2half_rn(v - __half2float(h));
    }
    CP_WAIT(0);
    __syncthreads();

    float acc[2][4][4];
#pragma unroll
    for (int a = 0; a < 2; a++)
#pragma unroll
        for (int b = 0; b < 4; b++)
#pragma unroll
            for (int c = 0; c < 4; c++) acc[a][b][c] = 0.0f;

    uint32_t offA[2], offB[2];
#pragma unroll
    for (int mi = 0; mi < 2; ++mi)
        offA[mi] = ((wm * 32 + mi * 16 + (lane & 15)) * 72 + (lane >> 4) * 8) * 2;
#pragma unroll
    for (int nj2 = 0; nj2 < 2; ++nj2)
        offB[nj2] = BH_OFF +
            ((wn * 32 + nj2 * 16 + (lane & 7) + ((lane >> 4) << 3)) * 72 +
             ((lane >> 3) & 1) * 8) * 2;

    compute_stage(sb, offA, offB, acc);
    epilogue_store(acc, bias, Oh, Ol, m0, n0, wm, wn, grp, q);
}

// ---------------------------------------------------------------------------
// final: ds/dt diagonals from H3 halves + output. One warp per output row.
__global__ __launch_bounds__(256) void final_kernel(
    const __half* __restrict__ Hh, const __half* __restrict__ Hl,
    const float* __restrict__ w4t,
    const float* __restrict__ sb4, const float* __restrict__ tb4,
    const float* __restrict__ x, float* __restrict__ out)
{
    const int wid = threadIdx.x >> 5, lane = threadIdx.x & 31;
    const int r = blockIdx.x * 8 + wid;
    const int i = r & 63;
    const __half* psh = Hh + (size_t)r * NDIM;
    const __half* psl = Hl + (size_t)r * NDIM;
    const __half* pth = Hh + (size_t)(r + HALF_M) * NDIM;
    const __half* ptl = Hl + (size_t)(r + HALF_M) * NDIM;
    const float* ws = w4t + i * 512;
    const float* wt = w4t + 32768 + i * 512;
    float ss = 0.0f, st = 0.0f;
#pragma unroll
    for (int k = lane; k < 512; k += 32) {
        ss += (__half2float(psh[k]) + __half2float(psl[k])) * ws[k];
        st += (__half2float(pth[k]) + __half2float(ptl[k])) * wt[k];
    }
#pragma unroll
    for (int off = 16; off; off >>= 1) {
        ss += __shfl_xor_sync(0xffffffffu, ss, off);
        st += __shfl_xor_sync(0xffffffffu, st, off);
    }
    if (lane == 0) {
        float dt = st + tb4[i];
        float ds = ss + sb4[i];
        out[r] = (x[r] - dt) * expf(-ds);
    }
}

// ---------------------------------------------------------------------------
extern "C" void kernel_launch(void* const* d_in, const int* in_sizes, int n_in,
                              void* d_out, int out_size)
{
    (void)in_sizes; (void)n_in; (void)out_size;

    const float* x    = (const float*)d_in[0];
    const float* koop = (const float*)d_in[1];
    const float* sW1 = (const float*)d_in[2];  const float* sb1 = (const float*)d_in[3];
    const float* sW2 = (const float*)d_in[4];  const float* sb2 = (const float*)d_in[5];
    const float* sW3 = (const float*)d_in[6];  const float* sb3 = (const float*)d_in[7];
    const float* sW4 = (const float*)d_in[8];  const float* sb4 = (const float*)d_in[9];
    const float* tW1 = (const float*)d_in[10]; const float* tb1 = (const float*)d_in[11];
    const float* tW2 = (const float*)d_in[12]; const float* tb2 = (const float*)d_in[13];
    const float* tW3 = (const float*)d_in[14]; const float* tb3 = (const float*)d_in[15];
    const float* tW4 = (const float*)d_in[16]; const float* tb4 = (const float*)d_in[17];
    float* out = (float*)d_out;

    __half *b0h, *b0l, *b1h, *b1l, *wh, *wl;
    float* w4t;
    cudaGetSymbolAddress((void**)&b0h, g_b0h);
    cudaGetSymbolAddress((void**)&b0l, g_b0l);
    cudaGetSymbolAddress((void**)&b1h, g_b1h);
    cudaGetSymbolAddress((void**)&b1l, g_b1l);
    cudaGetSymbolAddress((void**)&wh,  g_wh);
    cudaGetSymbolAddress((void**)&wl,  g_wl);
    cudaGetSymbolAddress((void**)&w4t, g_w4t);

    static int attr_done = 0;
    if (!attr_done) {
        cudaFuncSetAttribute(gemm512_kernel,
                             cudaFuncAttributeMaxDynamicSharedMemorySize, 2 * STAGE_BYTES);
        cudaFuncSetAttribute(gemm_l1_kernel,
                             cudaFuncAttributeMaxDynamicSharedMemorySize, STAGE_BYTES);
        attr_done = 1;
    }

    // weight prep (3 launches)
    prep_a  <<<dim3(16, 16, 4), dim3(32, 8)>>>(sW1, tW1, sW4, tW4, wh, wl, w4t);
    prep_w23<<<dim3(16, 16, 2), dim3(32, 8)>>>(sW2, sW3, wh, wl);
    prep_w23<<<dim3(16, 16, 2), dim3(32, 8)>>>(tW2, tW3, wh + MLP_STRIDE, wl + MLP_STRIDE);

    dim3 grid(8, MTOT / 128);
    // layer 1 (K=64, A from koopman)
    gemm_l1_kernel<<<grid, 256, STAGE_BYTES>>>(
        koop, wh + OFF_W1, wl + OFF_W1, wh + MLP_STRIDE + OFF_W1, wl + MLP_STRIDE + OFF_W1,
        sb1, tb1, b0h, b0l);
    // layer 2
    gemm512_kernel<<<grid, 256, 2 * STAGE_BYTES>>>(
        b0h, b0l, wh + OFF_W2, wl + OFF_W2, wh + MLP_STRIDE + OFF_W2, wl + MLP_STRIDE + OFF_W2,
        sb2, tb2, b1h, b1l);
    // layer 3
    gemm512_kernel<<<grid, 256, 2 * STAGE_BYTES>>>(
        b1h, b1l, wh + OFF_W3, wl + OFF_W3, wh + MLP_STRIDE + OFF_W3, wl + MLP_STRIDE + OFF_W3,
        sb3, tb3, b0h, b0l);
    // diagonal + output
    final_kernel<<<HALF_M / 8, 256>>>(b0h, b0l, w4t, sb4, tb4, x, out);
}